// round 3
// baseline (speedup 1.0000x reference)
#include <cuda_runtime.h>

namespace {
constexpr int B_    = 2;
constexpr int SQ_   = 2048;
constexpr int SK_   = 2048;
constexpr int HQ_   = 32;
constexpr int HKV_  = 8;
constexpr int GQ_   = HQ_ / HKV_;   // 4
constexpr int D_    = 128;
constexpr int D4_   = D_ / 4;       // 32
constexpr int WIN_  = 512;
constexpr int QT_   = 32;           // q rows per block
constexpr int KT_   = 128;          // kv rows per tile
constexpr int NTMAX_ = 5;           // ceil((512+32)/128) = 5
constexpr int STRIPW_ = NTMAX_ * KT_;   // 640
constexpr float SCALE_ = 0.088388347648318447f;  // 1/sqrt(128)
constexpr float CAP_   = 30.0f;

// Shared memory layout. K/V tile buffer is shared (V pass reuses Ks).
// Rows padded to 33 float4 (132 floats): row stride 132 words ≡ 4 (mod 32)
// -> lane-strided row access in QK inner loop is bank-conflict-free.
struct Smem {
  float4 Qs[QT_][33];        // 16896 B
  float4 Ks[KT_][33];        // 67584 B (K tile, then reused as V tile)
  float  P[QT_][STRIPW_];    // 81920 B  exp-score strip, later clipped probs
};
// total = 166400 B < 227 KB
}  // namespace

__global__ __launch_bounds__(256, 1)
void attn_swa_kernel(const float* __restrict__ q, const float* __restrict__ k,
                     const float* __restrict__ v, float* __restrict__ out) {
  extern __shared__ char smem_raw[];
  Smem& sm = *reinterpret_cast<Smem*>(smem_raw);

  const int tid  = threadIdx.x;
  const int w    = tid >> 5;   // warp 0..7 -> q rows 4w..4w+3
  const int lane = tid & 31;
  const int qtile = blockIdx.x;
  const int h     = blockIdx.y;
  const int b     = blockIdx.z;
  const int qs   = qtile * QT_;
  const int kvh  = h / GQ_;

  const int lo   = (qs > WIN_) ? (qs - WIN_) : 0;   // first allowed kv
  const int kend = qs + QT_;                        // exclusive kv bound (<= SK)
  const int nt   = (kend - lo + KT_ - 1) / KT_;     // 1..5 tiles

  // ---- load Q tile (coalesced float4) ----
  const float4* qg = reinterpret_cast<const float4*>(q) +
                     (((size_t)b * SQ_ + qs) * HQ_ + h) * D4_;
  for (int m = tid; m < QT_ * D4_; m += 256) {
    int r = m >> 5, d4 = m & 31;
    sm.Qs[r][d4] = qg[(size_t)r * (HQ_ * D4_) + d4];
  }
  __syncthreads();

  const float4* kbase = reinterpret_cast<const float4*>(k) +
                        ((size_t)b * SK_ * HKV_ + kvh) * D4_;
  const float4* vbase = reinterpret_cast<const float4*>(v) +
                        ((size_t)b * SK_ * HKV_ + kvh) * D4_;

  // =======================  QK pass  =======================
  for (int t = 0; t < nt; ++t) {
    const int jbase = lo + t * KT_;
    // load K tile (guarded; OOB rows -> 0, their scores get masked anyway)
    for (int m = tid; m < KT_ * D4_; m += 256) {
      int r = m >> 5, d4 = m & 31;
      int j = jbase + r;
      float4 val = make_float4(0.f, 0.f, 0.f, 0.f);
      if (j < kend) val = kbase[(size_t)j * (HKV_ * D4_) + d4];
      sm.Ks[r][d4] = val;
    }
    __syncthreads();

    // 4x4 micro-tile: rows 4w+i, kv cols lane+32*jj
    float acc[4][4];
#pragma unroll
    for (int i = 0; i < 4; ++i)
#pragma unroll
      for (int jj = 0; jj < 4; ++jj) acc[i][jj] = 0.f;

#pragma unroll 4
    for (int d4 = 0; d4 < D4_; ++d4) {
      float4 qa[4], kc[4];
#pragma unroll
      for (int i = 0; i < 4; ++i) qa[i] = sm.Qs[4 * w + i][d4];      // broadcast
#pragma unroll
      for (int jj = 0; jj < 4; ++jj) kc[jj] = sm.Ks[lane + 32 * jj][d4];  // conflict-free
#pragma unroll
      for (int i = 0; i < 4; ++i)
#pragma unroll
        for (int jj = 0; jj < 4; ++jj) {
          acc[i][jj] += qa[i].x * kc[jj].x;
          acc[i][jj] += qa[i].y * kc[jj].y;
          acc[i][jj] += qa[i].z * kc[jj].z;
          acc[i][jj] += qa[i].w * kc[jj].w;
        }
    }

    // cap (30*tanh(s/30)), mask, exp -> strip.
    // tanh(y) = 1 - 2/(exp(2y)+1): no overflow, capped logits in (-30,30).
#pragma unroll
    for (int i = 0; i < 4; ++i) {
      const int ig = qs + 4 * w + i;
#pragma unroll
      for (int jj = 0; jj < 4; ++jj) {
        const int jg = jbase + lane + 32 * jj;
        const bool ok = (jg >= ig - WIN_) && (jg <= ig);
        float y2 = acc[i][jj] * (2.0f * SCALE_ / CAP_);
        float ez = __expf(y2);
        float th = 1.0f - __fdividef(2.0f, ez + 1.0f);
        float e  = ok ? __expf(CAP_ * th) : 0.0f;
        sm.P[4 * w + i][t * KT_ + lane + 32 * jj] = e;
      }
    }
    __syncthreads();
  }

  // =======  row sums + clip transform (in place, per-warp rows)  =======
  const int width = nt * KT_;
#pragma unroll
  for (int i = 0; i < 4; ++i) {
    const int r = 4 * w + i;
    float s = 0.f;
    for (int c = lane; c < width; c += 32) s += sm.P[r][c];
#pragma unroll
    for (int o = 16; o; o >>= 1) s += __shfl_xor_sync(0xffffffffu, s, o);
    const float c1 = 1.02f / s;   // s > 0 always (diagonal key always allowed)
    for (int c = lane; c < width; c += 32) {
      float p = sm.P[r][c] * c1 - 0.01f;        // masked: 0*c1-0.01 -> clamps to 0
      sm.P[r][c] = fminf(fmaxf(p, 0.0f), 1.0f);
    }
  }
  __syncthreads();

  // =======================  PV pass  =======================
  float4 oacc[4];
#pragma unroll
  for (int i = 0; i < 4; ++i) oacc[i] = make_float4(0.f, 0.f, 0.f, 0.f);

  for (int t = 0; t < nt; ++t) {
    const int jbase = lo + t * KT_;
    for (int m = tid; m < KT_ * D4_; m += 256) {
      int r = m >> 5, d4 = m & 31;
      int j = jbase + r;
      float4 val = make_float4(0.f, 0.f, 0.f, 0.f);
      if (j < kend) val = vbase[(size_t)j * (HKV_ * D4_) + d4];
      sm.Ks[r][d4] = val;   // reuse buffer as V tile
    }
    __syncthreads();

    const int jmax = min(KT_, kend - jbase);
#pragma unroll 2
    for (int jj = 0; jj < jmax; ++jj) {
      float4 vv = sm.Ks[jj][lane];              // conflict-free (consecutive f4)
#pragma unroll
      for (int i = 0; i < 4; ++i) {
        float p = sm.P[4 * w + i][t * KT_ + jj];  // broadcast
        oacc[i].x += p * vv.x;
        oacc[i].y += p * vv.y;
        oacc[i].z += p * vv.z;
        oacc[i].w += p * vv.w;
      }
    }
    __syncthreads();
  }

  // ---- write output (coalesced float4) ----
  float4* og = reinterpret_cast<float4*>(out);
#pragma unroll
  for (int i = 0; i < 4; ++i) {
    size_t idx = (((size_t)b * SQ_ + qs + 4 * w + i) * HQ_ + h) * D4_ + lane;
    og[idx] = oacc[i];
  }
}

extern "C" void kernel_launch(void* const* d_in, const int* in_sizes, int n_in,
                              void* d_out, int out_size) {
  (void)in_sizes; (void)n_in; (void)out_size;
  const float* q = (const float*)d_in[0];
  const float* k = (const float*)d_in[1];
  const float* v = (const float*)d_in[2];
  float* out = (float*)d_out;

  static_assert(sizeof(Smem) <= 227 * 1024, "smem over budget");
  cudaFuncSetAttribute(attn_swa_kernel,
                       cudaFuncAttributeMaxDynamicSharedMemorySize,
                       (int)sizeof(Smem));
  dim3 grid(SQ_ / QT_, HQ_, B_);
  attn_swa_kernel<<<grid, 256, sizeof(Smem)>>>(q, k, v, out);
}

// round 5
// speedup vs baseline: 1.6602x; 1.6602x over previous
#include <cuda_runtime.h>
#include <cuda_bf16.h>
#include <stdint.h>

#define SQn 2048
#define HQn 32
#define HKVn 8
#define Dn 128
#define WINn 512
#define QTn 32
#define KTn 128
#define SPn 648              /* strip pitch (f32): 648 mod 32 = 8 -> conflict-light */
#define PQn 136              /* bf16 tile pitch: 272B rows -> LDSM conflict-free   */
#define SCALEf 0.088388347648318447f
#define CAPf 30.0f
#define KXf (SCALEf / CAPf)
#define C3f (-0.33333334f)
#define C5f (0.13333333f)
#define C7f (-0.05396825f)

// ---- smem layout (bytes) ----
#define O_QH 0
#define O_QL 8704
#define O_KH 17408
#define O_KL 52224
#define O_STRIP 87040        /* 32 x 648 f32 = 82944 */
#define O_SUMS 169984        /* 32 f32 */
#define SMEM_SZ 170112

__device__ __forceinline__ void ldsm4(uint32_t a, uint32_t r[4]) {
  asm volatile("ldmatrix.sync.aligned.m8n8.x4.shared.b16 {%0,%1,%2,%3}, [%4];"
               : "=r"(r[0]), "=r"(r[1]), "=r"(r[2]), "=r"(r[3]) : "r"(a));
}
__device__ __forceinline__ void ldsm4t(uint32_t a, uint32_t r[4]) {
  asm volatile("ldmatrix.sync.aligned.m8n8.x4.trans.shared.b16 {%0,%1,%2,%3}, [%4];"
               : "=r"(r[0]), "=r"(r[1]), "=r"(r[2]), "=r"(r[3]) : "r"(a));
}
__device__ __forceinline__ void mma16816(float c[4], const uint32_t a[4],
                                         uint32_t b0, uint32_t b1) {
  asm volatile(
      "mma.sync.aligned.m16n8k16.row.col.f32.bf16.bf16.f32 "
      "{%0,%1,%2,%3},{%4,%5,%6,%7},{%8,%9},{%0,%1,%2,%3};"
      : "+f"(c[0]), "+f"(c[1]), "+f"(c[2]), "+f"(c[3])
      : "r"(a[0]), "r"(a[1]), "r"(a[2]), "r"(a[3]), "r"(b0), "r"(b1));
}
__device__ __forceinline__ uint32_t s2u(const void* p) {
  uint32_t a;
  asm("{ .reg .u64 t; cvta.to.shared.u64 t, %1; cvt.u32.u64 %0, t; }" : "=r"(a) : "l"(p));
  return a;
}
// split pair of f32 into packed bf16x2 (hi) + packed bf16x2 (lo residual)
__device__ __forceinline__ void split2(float a, float b, uint32_t& hi, uint32_t& lo2) {
  __nv_bfloat16 ha = __float2bfloat16_rn(a), hb = __float2bfloat16_rn(b);
  __nv_bfloat16 la = __float2bfloat16_rn(a - __bfloat162float(ha));
  __nv_bfloat16 lb = __float2bfloat16_rn(b - __bfloat162float(hb));
  __nv_bfloat162 h2 = __halves2bfloat162(ha, hb), l2 = __halves2bfloat162(la, lb);
  hi = *reinterpret_cast<uint32_t*>(&h2);
  lo2 = *reinterpret_cast<uint32_t*>(&l2);
}
__device__ __forceinline__ float capexp(float s) {
  float xs = s * KXf, x2 = xs * xs;
  float pl = fmaf(x2, C7f, C5f);
  pl = fmaf(x2, pl, C3f);
  pl = fmaf(x2, pl, 1.0f);
  return __expf((CAPf * xs) * pl);
}

__global__ __launch_bounds__(256, 1)
void swa_mma(const float* __restrict__ q, const float* __restrict__ k,
             const float* __restrict__ v, float* __restrict__ out) {
  extern __shared__ char sm[];
  const uint32_t sb = s2u(sm);
  float* strip = reinterpret_cast<float*>(sm + O_STRIP);
  float* sums = reinterpret_cast<float*>(sm + O_SUMS);

  const int tid = threadIdx.x, w = tid >> 5, lane = tid & 31;
  const int mh = w & 1, nb = w >> 1;          // warp -> (m-half, n-quarter)
  const int quad = lane >> 2, c2 = (lane & 3) * 2;
  const int r0 = 16 * mh + quad, r1 = r0 + 8; // this thread's two q rows
  const int qtile = blockIdx.x, h = blockIdx.y, b = blockIdx.z;
  const int qs = qtile * QTn, kvh = h >> 2;
  const int lo = (qs > WINn) ? (qs - WINn) : 0;
  const int kend = qs + QTn;
  const int nt = (kend - lo + KTn - 1) >> 7;

  // ---- load + split Q (32 x 128) ----
  const float* q0 = q + ((size_t)(b * SQn + qs) * HQn + h) * Dn;
  for (int m = tid; m < QTn * 64; m += 256) {
    int r = m >> 6, dp = m & 63;
    float2 vv = *reinterpret_cast<const float2*>(q0 + (size_t)r * (HQn * Dn) + 2 * dp);
    uint32_t hi, lo2;
    split2(vv.x, vv.y, hi, lo2);
    uint32_t off = (uint32_t)(r * PQn + 2 * dp) * 2;
    *reinterpret_cast<uint32_t*>(sm + O_QH + off) = hi;
    *reinterpret_cast<uint32_t*>(sm + O_QL + off) = lo2;
  }

  const float* kb = k + ((size_t)b * SQn * HKVn + kvh) * Dn;
  const float* vb = v + ((size_t)b * SQn * HKVn + kvh) * Dn;

  // precomputed ldmatrix lane offsets
  const int aRow = 16 * mh + (lane & 7) + 8 * ((lane >> 3) & 1);
  const int aColB = 8 * ((lane >> 4) & 1);
  const int kRow = (lane & 7) + 8 * ((lane >> 4) & 1);  // QK B: bit4 -> kv+8
  const int kColB = 8 * ((lane >> 3) & 1);              // QK B: bit3 -> d+8
  const int vRow = (lane & 7) + 8 * ((lane >> 3) & 1);  // PV B: bit3 -> kv+8
  const int vColB = 8 * ((lane >> 4) & 1);              // PV B: bit4 -> d+8

  // ======================= QK phase =======================
  for (int t = 0; t < nt; ++t) {
    const int jb = lo + t * KTn;
    __syncthreads();
    for (int m = tid; m < KTn * 64; m += 256) {
      int r = m >> 6, dp = m & 63, j = jb + r;
      float2 vv = make_float2(0.f, 0.f);
      if (j < kend) vv = *reinterpret_cast<const float2*>(kb + (size_t)j * (HKVn * Dn) + 2 * dp);
      uint32_t hi, lo2;
      split2(vv.x, vv.y, hi, lo2);
      uint32_t off = (uint32_t)(r * PQn + 2 * dp) * 2;
      *reinterpret_cast<uint32_t*>(sm + O_KH + off) = hi;
      *reinterpret_cast<uint32_t*>(sm + O_KL + off) = lo2;
    }
    __syncthreads();

    float acc[4][4] = {};
#pragma unroll
    for (int ks = 0; ks < 8; ++ks) {
      uint32_t ah[4], al[4], bh[4], bl[4];
      uint32_t aoff = (uint32_t)(aRow * PQn + 16 * ks + aColB) * 2;
      ldsm4(sb + O_QH + aoff, ah);
      ldsm4(sb + O_QL + aoff, al);
#pragma unroll
      for (int p = 0; p < 2; ++p) {
        uint32_t boff = (uint32_t)((32 * nb + 16 * p + kRow) * PQn + 16 * ks + kColB) * 2;
        ldsm4(sb + O_KH + boff, bh);
        ldsm4(sb + O_KL + boff, bl);
        mma16816(acc[2 * p], ah, bh[0], bh[1]);
        mma16816(acc[2 * p], ah, bl[0], bl[1]);
        mma16816(acc[2 * p], al, bh[0], bh[1]);
        mma16816(acc[2 * p + 1], ah, bh[2], bh[3]);
        mma16816(acc[2 * p + 1], ah, bl[2], bl[3]);
        mma16816(acc[2 * p + 1], al, bh[2], bh[3]);
      }
    }
    // epilogue: cap/exp/mask -> strip
    const int i0 = qs + r0, i1 = qs + r1;
#pragma unroll
    for (int j4 = 0; j4 < 4; ++j4) {
      const int cb = 32 * nb + 8 * j4 + c2;
      const int jg = jb + cb;
      float e00 = capexp(acc[j4][0]), e01 = capexp(acc[j4][1]);
      float e10 = capexp(acc[j4][2]), e11 = capexp(acc[j4][3]);
      e00 = (jg >= i0 - WINn && jg <= i0) ? e00 : 0.f;
      e01 = (jg + 1 >= i0 - WINn && jg + 1 <= i0) ? e01 : 0.f;
      e10 = (jg >= i1 - WINn && jg <= i1) ? e10 : 0.f;
      e11 = (jg + 1 >= i1 - WINn && jg + 1 <= i1) ? e11 : 0.f;
      *reinterpret_cast<float2*>(&strip[r0 * SPn + t * KTn + cb]) = make_float2(e00, e01);
      *reinterpret_cast<float2*>(&strip[r1 * SPn + t * KTn + cb]) = make_float2(e10, e11);
    }
  }
  __syncthreads();

  // ======================= row sums =======================
  const int width = nt * KTn;
#pragma unroll
  for (int i = 0; i < 4; ++i) {
    const int r = 4 * w + i;
    float s = 0.f;
    for (int c = lane; c < width; c += 32) s += strip[r * SPn + c];
#pragma unroll
    for (int o = 16; o; o >>= 1) s += __shfl_xor_sync(0xffffffffu, s, o);
    if (lane == 0) sums[r] = 1.02f / s;
  }
  __syncthreads();

  // ======================= PV phase =======================
  const float c1a = sums[r0], c1b = sums[r1];
  float oacc[4][4] = {};
  for (int t = 0; t < nt; ++t) {
    const int jb = lo + t * KTn;
    __syncthreads();
    for (int m = tid; m < KTn * 64; m += 256) {
      int r = m >> 6, dp = m & 63, j = jb + r;
      float2 vv = make_float2(0.f, 0.f);
      if (j < kend) vv = *reinterpret_cast<const float2*>(vb + (size_t)j * (HKVn * Dn) + 2 * dp);
      uint32_t hi, lo2;
      split2(vv.x, vv.y, hi, lo2);
      uint32_t off = (uint32_t)(r * PQn + 2 * dp) * 2;
      *reinterpret_cast<uint32_t*>(sm + O_KH + off) = hi;   // VH
      *reinterpret_cast<uint32_t*>(sm + O_KL + off) = lo2;  // VL
    }
    __syncthreads();

#pragma unroll
    for (int ks = 0; ks < 8; ++ks) {
      // build P fragments from strip (fused clip + split)
      const int colb = t * KTn + 16 * ks + c2;
      float2 p00 = *reinterpret_cast<const float2*>(&strip[r0 * SPn + colb]);
      float2 p01 = *reinterpret_cast<const float2*>(&strip[r0 * SPn + colb + 8]);
      float2 p10 = *reinterpret_cast<const float2*>(&strip[r1 * SPn + colb]);
      float2 p11 = *reinterpret_cast<const float2*>(&strip[r1 * SPn + colb + 8]);
      float a00 = fminf(fmaxf(fmaf(p00.x, c1a, -0.01f), 0.f), 1.f);
      float a01 = fminf(fmaxf(fmaf(p00.y, c1a, -0.01f), 0.f), 1.f);
      float a02 = fminf(fmaxf(fmaf(p01.x, c1a, -0.01f), 0.f), 1.f);
      float a03 = fminf(fmaxf(fmaf(p01.y, c1a, -0.01f), 0.f), 1.f);
      float a10 = fminf(fmaxf(fmaf(p10.x, c1b, -0.01f), 0.f), 1.f);
      float a11 = fminf(fmaxf(fmaf(p10.y, c1b, -0.01f), 0.f), 1.f);
      float a12 = fminf(fmaxf(fmaf(p11.x, c1b, -0.01f), 0.f), 1.f);
      float a13 = fminf(fmaxf(fmaf(p11.y, c1b, -0.01f), 0.f), 1.f);
      uint32_t ah[4], al[4];
      split2(a00, a01, ah[0], al[0]);  // (r0, cols c2,c2+1)
      split2(a10, a11, ah[1], al[1]);  // (r1, cols c2,c2+1)
      split2(a02, a03, ah[2], al[2]);  // (r0, cols c2+8,+9)
      split2(a12, a13, ah[3], al[3]);  // (r1, cols c2+8,+9)
#pragma unroll
      for (int p = 0; p < 2; ++p) {
        uint32_t bh[4], bl[4];
        uint32_t boff = (uint32_t)((16 * ks + vRow) * PQn + 32 * nb + 16 * p + vColB) * 2;
        ldsm4t(sb + O_KH + boff, bh);
        ldsm4t(sb + O_KL + boff, bl);
        mma16816(oacc[2 * p], ah, bh[0], bh[1]);
        mma16816(oacc[2 * p], ah, bl[0], bl[1]);
        mma16816(oacc[2 * p], al, bh[0], bh[1]);
        mma16816(oacc[2 * p + 1], ah, bh[2], bh[3]);
        mma16816(oacc[2 * p + 1], ah, bl[2], bl[3]);
        mma16816(oacc[2 * p + 1], al, bh[2], bh[3]);
      }
    }
  }

  // ---- stage output through strip, then coalesced store ----
  __syncthreads();
#pragma unroll
  for (int j4 = 0; j4 < 4; ++j4) {
    const int cb = 32 * nb + 8 * j4 + c2;
    *reinterpret_cast<float2*>(&strip[r0 * SPn + cb]) = make_float2(oacc[j4][0], oacc[j4][1]);
    *reinterpret_cast<float2*>(&strip[r1 * SPn + cb]) = make_float2(oacc[j4][2], oacc[j4][3]);
  }
  __syncthreads();
  float* ob = out + ((size_t)(b * SQn + qs) * HQn + h) * Dn;
  for (int m = tid; m < QTn * 32; m += 256) {
    int r = m >> 5, d4 = m & 31;
    *reinterpret_cast<float4*>(ob + (size_t)r * (HQn * Dn) + 4 * d4) =
        *reinterpret_cast<const float4*>(&strip[r * SPn + 4 * d4]);
  }
}

extern "C" void kernel_launch(void* const* d_in, const int* in_sizes, int n_in,
                              void* d_out, int out_size) {
  (void)in_sizes; (void)n_in; (void)out_size;
  const float* q = (const float*)d_in[0];
  const float* k = (const float*)d_in[1];
  const float* v = (const float*)d_in[2];
  float* out = (float*)d_out;
  cudaFuncSetAttribute(swa_mma, cudaFuncAttributeMaxDynamicSharedMemorySize, SMEM_SZ);
  dim3 grid(SQn / QTn, HQn, 2);
  swa_mma<<<grid, 256, SMEM_SZ>>>(q, k, v, out);
}

// round 6
// speedup vs baseline: 3.3028x; 1.9893x over previous
#include <cuda_runtime.h>
#include <cuda_bf16.h>
#include <stdint.h>

#define SQn 2048
#define HQn 32
#define HKVn 8
#define Dn 128
#define WINn 512
#define QTn 32
#define KTn 128
#define NQTn 64              /* q tiles per (b,h) */
#define NCTAn 4096
#define SPn 640              /* gmem strip pitch (f32) */
#define PQn 136              /* bf16 tile pitch: 272B rows -> LDSM conflict-free */
#define SCALEf 0.088388347648318447f
#define CAPf 30.0f
#define KXf (SCALEf / CAPf)
#define C3f (-0.33333334f)
#define C5f (0.13333333f)
#define C7f (-0.05396825f)

// ---- smem layout (bytes) ----
#define O_QH 0
#define O_QL 8704
#define O_KH 17408
#define O_KL 52224
#define O_SUMS 87040         /* 32 f32 */
#define SMEM_SZ 87168

__device__ float g_strip[(size_t)NCTAn * QTn * SPn];   // 336 MB scratch (L2-resident working set)

__device__ __forceinline__ void ldsm4(uint32_t a, uint32_t r[4]) {
  asm volatile("ldmatrix.sync.aligned.m8n8.x4.shared.b16 {%0,%1,%2,%3}, [%4];"
               : "=r"(r[0]), "=r"(r[1]), "=r"(r[2]), "=r"(r[3]) : "r"(a));
}
__device__ __forceinline__ void ldsm4t(uint32_t a, uint32_t r[4]) {
  asm volatile("ldmatrix.sync.aligned.m8n8.x4.trans.shared.b16 {%0,%1,%2,%3}, [%4];"
               : "=r"(r[0]), "=r"(r[1]), "=r"(r[2]), "=r"(r[3]) : "r"(a));
}
__device__ __forceinline__ void mma16816(float c[4], const uint32_t a[4],
                                         uint32_t b0, uint32_t b1) {
  asm volatile(
      "mma.sync.aligned.m16n8k16.row.col.f32.bf16.bf16.f32 "
      "{%0,%1,%2,%3},{%4,%5,%6,%7},{%8,%9},{%0,%1,%2,%3};"
      : "+f"(c[0]), "+f"(c[1]), "+f"(c[2]), "+f"(c[3])
      : "r"(a[0]), "r"(a[1]), "r"(a[2]), "r"(a[3]), "r"(b0), "r"(b1));
}
__device__ __forceinline__ uint32_t s2u(const void* p) {
  uint32_t a;
  asm("{ .reg .u64 t; cvta.to.shared.u64 t, %1; cvt.u32.u64 %0, t; }" : "=r"(a) : "l"(p));
  return a;
}
__device__ __forceinline__ void split2(float a, float b, uint32_t& hi, uint32_t& lo2) {
  __nv_bfloat16 ha = __float2bfloat16_rn(a), hb = __float2bfloat16_rn(b);
  __nv_bfloat16 la = __float2bfloat16_rn(a - __bfloat162float(ha));
  __nv_bfloat16 lb = __float2bfloat16_rn(b - __bfloat162float(hb));
  __nv_bfloat162 h2 = __halves2bfloat162(ha, hb), l2 = __halves2bfloat162(la, lb);
  hi = *reinterpret_cast<uint32_t*>(&h2);
  lo2 = *reinterpret_cast<uint32_t*>(&l2);
}
__device__ __forceinline__ float capexp(float s) {
  float xs = s * KXf, x2 = xs * xs;
  float pl = fmaf(x2, C7f, C5f);
  pl = fmaf(x2, pl, C3f);
  pl = fmaf(x2, pl, 1.0f);
  return __expf((CAPf * xs) * pl);
}

__global__ __launch_bounds__(256, 2)
void swa_mma(const float* __restrict__ q, const float* __restrict__ k,
             const float* __restrict__ v, float* __restrict__ out) {
  extern __shared__ char sm[];
  const uint32_t sb = s2u(sm);
  float* sums = reinterpret_cast<float*>(sm + O_SUMS);

  const int tid = threadIdx.x, w = tid >> 5, lane = tid & 31;
  const int mh = w & 1, nb = w >> 1;          // warp -> (m-half, n-quarter)
  const int quad = lane >> 2, c2 = (lane & 3) * 2;
  const int r0 = 16 * mh + quad, r1 = r0 + 8; // this thread's two q rows
  const int qtile = blockIdx.x, h = blockIdx.y, b = blockIdx.z;
  const int qs = qtile * QTn, kvh = h >> 2;
  const int lo = (qs > WINn) ? (qs - WINn) : 0;
  const int kend = qs + QTn;
  const int nt = (kend - lo + KTn - 1) >> 7;
  const int cta = (b * HQn + h) * NQTn + qtile;
  float* __restrict__ strip = g_strip + (size_t)cta * (QTn * SPn);

  // ---- init sums + load/split Q (32 x 128) ----
  if (tid < QTn) sums[tid] = 0.f;
  const float* q0 = q + ((size_t)(b * SQn + qs) * HQn + h) * Dn;
  for (int m = tid; m < QTn * 64; m += 256) {
    int r = m >> 6, dp = m & 63;
    float2 vv = *reinterpret_cast<const float2*>(q0 + (size_t)r * (HQn * Dn) + 2 * dp);
    uint32_t hi, lo2;
    split2(vv.x, vv.y, hi, lo2);
    uint32_t off = (uint32_t)(r * PQn + 2 * dp) * 2;
    *reinterpret_cast<uint32_t*>(sm + O_QH + off) = hi;
    *reinterpret_cast<uint32_t*>(sm + O_QL + off) = lo2;
  }

  const float* kb = k + ((size_t)b * SQn * HKVn + kvh) * Dn;
  const float* vb = v + ((size_t)b * SQn * HKVn + kvh) * Dn;

  // ldmatrix lane offsets
  const int aRow = 16 * mh + (lane & 7) + 8 * ((lane >> 3) & 1);
  const int aColB = 8 * ((lane >> 4) & 1);
  const int kRow = (lane & 7) + 8 * ((lane >> 4) & 1);
  const int kColB = 8 * ((lane >> 3) & 1);
  const int vRow = (lane & 7) + 8 * ((lane >> 3) & 1);
  const int vColB = 8 * ((lane >> 4) & 1);

  // ======================= QK phase =======================
  float ssum0 = 0.f, ssum1 = 0.f;
  for (int t = 0; t < nt; ++t) {
    const int jb = lo + t * KTn;
    __syncthreads();
    for (int m = tid; m < KTn * 64; m += 256) {
      int r = m >> 6, dp = m & 63, j = jb + r;
      float2 vv = make_float2(0.f, 0.f);
      if (j < kend) vv = *reinterpret_cast<const float2*>(kb + (size_t)j * (HKVn * Dn) + 2 * dp);
      uint32_t hi, lo2;
      split2(vv.x, vv.y, hi, lo2);
      uint32_t off = (uint32_t)(r * PQn + 2 * dp) * 2;
      *reinterpret_cast<uint32_t*>(sm + O_KH + off) = hi;
      *reinterpret_cast<uint32_t*>(sm + O_KL + off) = lo2;
    }
    __syncthreads();

    float acc[4][4] = {};
#pragma unroll
    for (int ks = 0; ks < 8; ++ks) {
      uint32_t ah[4], al[4], bh[4], bl[4];
      uint32_t aoff = (uint32_t)(aRow * PQn + 16 * ks + aColB) * 2;
      ldsm4(sb + O_QH + aoff, ah);
      ldsm4(sb + O_QL + aoff, al);
#pragma unroll
      for (int p = 0; p < 2; ++p) {
        uint32_t boff = (uint32_t)((32 * nb + 16 * p + kRow) * PQn + 16 * ks + kColB) * 2;
        ldsm4(sb + O_KH + boff, bh);
        ldsm4(sb + O_KL + boff, bl);
        mma16816(acc[2 * p], ah, bh[0], bh[1]);
        mma16816(acc[2 * p], ah, bl[0], bl[1]);
        mma16816(acc[2 * p], al, bh[0], bh[1]);
        mma16816(acc[2 * p + 1], ah, bh[2], bh[3]);
        mma16816(acc[2 * p + 1], ah, bl[2], bl[3]);
        mma16816(acc[2 * p + 1], al, bh[2], bh[3]);
      }
    }
    // epilogue: cap/exp/mask -> gmem strip + register sums
    const int i0 = qs + r0, i1 = qs + r1;
#pragma unroll
    for (int j4 = 0; j4 < 4; ++j4) {
      const int cb = 32 * nb + 8 * j4 + c2;
      const int jg = jb + cb;
      float e00 = capexp(acc[j4][0]), e01 = capexp(acc[j4][1]);
      float e10 = capexp(acc[j4][2]), e11 = capexp(acc[j4][3]);
      e00 = (jg >= i0 - WINn && jg <= i0) ? e00 : 0.f;
      e01 = (jg + 1 >= i0 - WINn && jg + 1 <= i0) ? e01 : 0.f;
      e10 = (jg >= i1 - WINn && jg <= i1) ? e10 : 0.f;
      e11 = (jg + 1 >= i1 - WINn && jg + 1 <= i1) ? e11 : 0.f;
      ssum0 += e00 + e01;
      ssum1 += e10 + e11;
      *reinterpret_cast<float2*>(&strip[r0 * SPn + t * KTn + cb]) = make_float2(e00, e01);
      *reinterpret_cast<float2*>(&strip[r1 * SPn + t * KTn + cb]) = make_float2(e10, e11);
    }
  }

  // ---- row sums: 4-lane shfl reduce, then one atomic per row ----
  ssum0 += __shfl_xor_sync(0xffffffffu, ssum0, 1);
  ssum0 += __shfl_xor_sync(0xffffffffu, ssum0, 2);
  ssum1 += __shfl_xor_sync(0xffffffffu, ssum1, 1);
  ssum1 += __shfl_xor_sync(0xffffffffu, ssum1, 2);
  if ((lane & 3) == 0) {
    atomicAdd(&sums[r0], ssum0);
    atomicAdd(&sums[r1], ssum1);
  }
  __syncthreads();

  // ======================= PV phase =======================
  const float c1a = 1.02f / sums[r0], c1b = 1.02f / sums[r1];
  float oacc[4][4] = {};
  for (int t = 0; t < nt; ++t) {
    const int jb = lo + t * KTn;
    __syncthreads();
    for (int m = tid; m < KTn * 64; m += 256) {
      int r = m >> 6, dp = m & 63, j = jb + r;
      float2 vv = make_float2(0.f, 0.f);
      if (j < kend) vv = *reinterpret_cast<const float2*>(vb + (size_t)j * (HKVn * Dn) + 2 * dp);
      uint32_t hi, lo2;
      split2(vv.x, vv.y, hi, lo2);
      uint32_t off = (uint32_t)(r * PQn + 2 * dp) * 2;
      *reinterpret_cast<uint32_t*>(sm + O_KH + off) = hi;   // VH
      *reinterpret_cast<uint32_t*>(sm + O_KL + off) = lo2;  // VL
    }
    __syncthreads();

#pragma unroll
    for (int ks = 0; ks < 8; ++ks) {
      const int colb = t * KTn + 16 * ks + c2;
      float2 p00 = *reinterpret_cast<const float2*>(&strip[r0 * SPn + colb]);
      float2 p01 = *reinterpret_cast<const float2*>(&strip[r0 * SPn + colb + 8]);
      float2 p10 = *reinterpret_cast<const float2*>(&strip[r1 * SPn + colb]);
      float2 p11 = *reinterpret_cast<const float2*>(&strip[r1 * SPn + colb + 8]);
      float a00 = fminf(fmaxf(fmaf(p00.x, c1a, -0.01f), 0.f), 1.f);
      float a01 = fminf(fmaxf(fmaf(p00.y, c1a, -0.01f), 0.f), 1.f);
      float a02 = fminf(fmaxf(fmaf(p01.x, c1a, -0.01f), 0.f), 1.f);
      float a03 = fminf(fmaxf(fmaf(p01.y, c1a, -0.01f), 0.f), 1.f);
      float a10 = fminf(fmaxf(fmaf(p10.x, c1b, -0.01f), 0.f), 1.f);
      float a11 = fminf(fmaxf(fmaf(p10.y, c1b, -0.01f), 0.f), 1.f);
      float a12 = fminf(fmaxf(fmaf(p11.x, c1b, -0.01f), 0.f), 1.f);
      float a13 = fminf(fmaxf(fmaf(p11.y, c1b, -0.01f), 0.f), 1.f);
      uint32_t ah[4], al[4];
      split2(a00, a01, ah[0], al[0]);
      split2(a10, a11, ah[1], al[1]);
      split2(a02, a03, ah[2], al[2]);
      split2(a12, a13, ah[3], al[3]);
#pragma unroll
      for (int p = 0; p < 2; ++p) {
        uint32_t bh[4], bl[4];
        uint32_t boff = (uint32_t)((16 * ks + vRow) * PQn + 32 * nb + 16 * p + vColB) * 2;
        ldsm4t(sb + O_KH + boff, bh);
        ldsm4t(sb + O_KL + boff, bl);
        mma16816(oacc[2 * p], ah, bh[0], bh[1]);
        mma16816(oacc[2 * p], ah, bl[0], bl[1]);
        mma16816(oacc[2 * p], al, bh[0], bh[1]);
        mma16816(oacc[2 * p + 1], ah, bh[2], bh[3]);
        mma16816(oacc[2 * p + 1], ah, bl[2], bl[3]);
        mma16816(oacc[2 * p + 1], al, bh[2], bh[3]);
      }
    }
  }

  // ---- stage output through smem (reuse K/V buffer), coalesced store ----
  __syncthreads();
  float* ostage = reinterpret_cast<float*>(sm + O_KH);   // 32 x 132 f32
#pragma unroll
  for (int j4 = 0; j4 < 4; ++j4) {
    const int cb = 32 * nb + 8 * j4 + c2;
    *reinterpret_cast<float2*>(&ostage[r0 * 132 + cb]) = make_float2(oacc[j4][0], oacc[j4][1]);
    *reinterpret_cast<float2*>(&ostage[r1 * 132 + cb]) = make_float2(oacc[j4][2], oacc[j4][3]);
  }
  __syncthreads();
  float* ob = out + ((size_t)(b * SQn + qs) * HQn + h) * Dn;
  for (int m = tid; m < QTn * 32; m += 256) {
    int r = m >> 5, d4 = m & 31;
    *reinterpret_cast<float4*>(ob + (size_t)r * (HQn * Dn) + 4 * d4) =
        *reinterpret_cast<const float4*>(&ostage[r * 132 + 4 * d4]);
  }
}

extern "C" void kernel_launch(void* const* d_in, const int* in_sizes, int n_in,
                              void* d_out, int out_size) {
  (void)in_sizes; (void)n_in; (void)out_size;
  const float* q = (const float*)d_in[0];
  const float* k = (const float*)d_in[1];
  const float* v = (const float*)d_in[2];
  float* out = (float*)d_out;
  cudaFuncSetAttribute(swa_mma, cudaFuncAttributeMaxDynamicSharedMemorySize, SMEM_SZ);
  dim3 grid(SQn / QTn, HQn, 2);
  swa_mma<<<grid, 256, SMEM_SZ>>>(q, k, v, out);
}

// round 7
// speedup vs baseline: 3.7987x; 1.1501x over previous
#include <cuda_runtime.h>
#include <cuda_bf16.h>
#include <stdint.h>

#define SQn 2048
#define HQn 32
#define HKVn 8
#define Dn 128
#define WINn 512
#define QPn 8                /* q positions per CTA */
#define QTn 32               /* rows per CTA = QPn * 4 heads */
#define KTn 128
#define NQBn 256             /* q blocks = SQn / QPn */
#define NCTAn 4096
#define SPn 640              /* gmem strip pitch (f32) */
#define PQn 136              /* bf16 tile pitch: 272B rows -> LDSM conflict-free */
#define SCALEf 0.088388347648318447f
#define CAPf 30.0f
#define KXf (SCALEf / CAPf)
#define C3f (-0.33333334f)
#define C5f (0.13333333f)
#define C7f (-0.05396825f)

// ---- smem layout (bytes) ----
#define O_QH 0
#define O_QL 8704
#define O_KH 17408
#define O_KL 52224
#define O_SUMS 87040         /* 32 f32 */
#define SMEM_SZ 87168

__device__ float g_strip[(size_t)NCTAn * QTn * SPn];   // L2-resident scratch

__device__ __forceinline__ void ldsm4(uint32_t a, uint32_t r[4]) {
  asm volatile("ldmatrix.sync.aligned.m8n8.x4.shared.b16 {%0,%1,%2,%3}, [%4];"
               : "=r"(r[0]), "=r"(r[1]), "=r"(r[2]), "=r"(r[3]) : "r"(a));
}
__device__ __forceinline__ void ldsm4t(uint32_t a, uint32_t r[4]) {
  asm volatile("ldmatrix.sync.aligned.m8n8.x4.trans.shared.b16 {%0,%1,%2,%3}, [%4];"
               : "=r"(r[0]), "=r"(r[1]), "=r"(r[2]), "=r"(r[3]) : "r"(a));
}
__device__ __forceinline__ void mma16816(float c[4], const uint32_t a[4],
                                         uint32_t b0, uint32_t b1) {
  asm volatile(
      "mma.sync.aligned.m16n8k16.row.col.f32.bf16.bf16.f32 "
      "{%0,%1,%2,%3},{%4,%5,%6,%7},{%8,%9},{%0,%1,%2,%3};"
      : "+f"(c[0]), "+f"(c[1]), "+f"(c[2]), "+f"(c[3])
      : "r"(a[0]), "r"(a[1]), "r"(a[2]), "r"(a[3]), "r"(b0), "r"(b1));
}
__device__ __forceinline__ uint32_t s2u(const void* p) {
  uint32_t a;
  asm("{ .reg .u64 t; cvta.to.shared.u64 t, %1; cvt.u32.u64 %0, t; }" : "=r"(a) : "l"(p));
  return a;
}
__device__ __forceinline__ void split2(float a, float b, uint32_t& hi, uint32_t& lo2) {
  __nv_bfloat16 ha = __float2bfloat16_rn(a), hb = __float2bfloat16_rn(b);
  __nv_bfloat16 la = __float2bfloat16_rn(a - __bfloat162float(ha));
  __nv_bfloat16 lb = __float2bfloat16_rn(b - __bfloat162float(hb));
  __nv_bfloat162 h2 = __halves2bfloat162(ha, hb), l2 = __halves2bfloat162(la, lb);
  hi = *reinterpret_cast<uint32_t*>(&h2);
  lo2 = *reinterpret_cast<uint32_t*>(&l2);
}
__device__ __forceinline__ void split4(float4 v, uint2& hi, uint2& lo) {
  split2(v.x, v.y, hi.x, lo.x);
  split2(v.z, v.w, hi.y, lo.y);
}
__device__ __forceinline__ float capexp(float s) {
  float xs = s * KXf, x2 = xs * xs;
  float pl = fmaf(x2, C7f, C5f);
  pl = fmaf(x2, pl, C3f);
  pl = fmaf(x2, pl, 1.0f);
  return __expf((CAPf * xs) * pl);
}

__global__ __launch_bounds__(256, 2)
void swa_mma(const float* __restrict__ q, const float* __restrict__ k,
             const float* __restrict__ v, float* __restrict__ out) {
  extern __shared__ char sm[];
  const uint32_t sb = s2u(sm);
  float* sums = reinterpret_cast<float*>(sm + O_SUMS);

  const int tid = threadIdx.x, w = tid >> 5, lane = tid & 31;
  const int mh = w & 1, nb = w >> 1;          // warp -> (m-half, n-quarter)
  const int quad = lane >> 2, c2 = (lane & 3) * 2;
  const int r0 = 16 * mh + quad, r1 = r0 + 8; // rows: same q-pos, adjacent heads
  const int qb = blockIdx.x, kvh = blockIdx.y, b = blockIdx.z;
  const int qs8 = qb * QPn;
  const int lo = (qs8 > WINn) ? (qs8 - WINn) : 0;
  const int kend = qs8 + QPn;                 // exclusive kv bound
  const int nt = (kend - lo + KTn - 1) >> 7;
  const int cta = (b * HKVn + kvh) * NQBn + qb;
  float* __restrict__ strip = g_strip + (size_t)cta * (QTn * SPn);

  // ---- init sums + load/split Q (32 rows = 4 heads x 8 qpos, 128 d) ----
  if (tid < QTn) sums[tid] = 0.f;
  for (int m = tid; m < QTn * 32; m += 256) {
    int r = m >> 5, d4 = m & 31;
    const float* qp = q + (((size_t)(b * SQn + qs8 + (r & 7)) * HQn) + kvh * 4 + (r >> 3)) * Dn;
    float4 vv = *reinterpret_cast<const float4*>(qp + 4 * d4);
    uint2 hi, lo2;
    split4(vv, hi, lo2);
    uint32_t off = (uint32_t)(r * PQn + 4 * d4) * 2;
    *reinterpret_cast<uint2*>(sm + O_QH + off) = hi;
    *reinterpret_cast<uint2*>(sm + O_QL + off) = lo2;
  }

  const float* kb = k + ((size_t)b * SQn * HKVn + kvh) * Dn;
  const float* vb = v + ((size_t)b * SQn * HKVn + kvh) * Dn;

  // ldmatrix lane offsets
  const int aRow = 16 * mh + (lane & 7) + 8 * ((lane >> 3) & 1);
  const int aColB = 8 * ((lane >> 4) & 1);
  const int kRow = (lane & 7) + 8 * ((lane >> 4) & 1);
  const int kColB = 8 * ((lane >> 3) & 1);
  const int vRow = (lane & 7) + 8 * ((lane >> 3) & 1);
  const int vColB = 8 * ((lane >> 4) & 1);

  // ======================= QK phase =======================
  float ssum0 = 0.f, ssum1 = 0.f;
  const int i0 = qs8 + quad;                  // q position for BOTH r0 and r1
  for (int t = 0; t < nt; ++t) {
    const int jb = lo + t * KTn;
    __syncthreads();
    for (int m = tid; m < KTn * 32; m += 256) {
      int r = m >> 5, d4 = m & 31, j = jb + r;
      float4 vv = make_float4(0.f, 0.f, 0.f, 0.f);
      if (j < kend) vv = *reinterpret_cast<const float4*>(kb + (size_t)j * (HKVn * Dn) + 4 * d4);
      uint2 hi, lo2;
      split4(vv, hi, lo2);
      uint32_t off = (uint32_t)(r * PQn + 4 * d4) * 2;
      *reinterpret_cast<uint2*>(sm + O_KH + off) = hi;
      *reinterpret_cast<uint2*>(sm + O_KL + off) = lo2;
    }
    __syncthreads();

    float acc[4][4] = {};
#pragma unroll
    for (int ks = 0; ks < 8; ++ks) {
      uint32_t ah[4], al[4], bh[4], bl[4];
      uint32_t aoff = (uint32_t)(aRow * PQn + 16 * ks + aColB) * 2;
      ldsm4(sb + O_QH + aoff, ah);
      ldsm4(sb + O_QL + aoff, al);
#pragma unroll
      for (int p = 0; p < 2; ++p) {
        uint32_t boff = (uint32_t)((32 * nb + 16 * p + kRow) * PQn + 16 * ks + kColB) * 2;
        ldsm4(sb + O_KH + boff, bh);
        ldsm4(sb + O_KL + boff, bl);
        mma16816(acc[2 * p], ah, bh[0], bh[1]);
        mma16816(acc[2 * p], ah, bl[0], bl[1]);
        mma16816(acc[2 * p], al, bh[0], bh[1]);
        mma16816(acc[2 * p + 1], ah, bh[2], bh[3]);
        mma16816(acc[2 * p + 1], ah, bl[2], bl[3]);
        mma16816(acc[2 * p + 1], al, bh[2], bh[3]);
      }
    }
    // epilogue: cap/exp/mask -> gmem strip + register sums
#pragma unroll
    for (int j4 = 0; j4 < 4; ++j4) {
      const int cb = 32 * nb + 8 * j4 + c2;
      const int jg = jb + cb;
      const bool ok0 = (jg >= i0 - WINn) && (jg <= i0);
      const bool ok1 = (jg + 1 >= i0 - WINn) && (jg + 1 <= i0);
      float e00 = ok0 ? capexp(acc[j4][0]) : 0.f;
      float e01 = ok1 ? capexp(acc[j4][1]) : 0.f;
      float e10 = ok0 ? capexp(acc[j4][2]) : 0.f;
      float e11 = ok1 ? capexp(acc[j4][3]) : 0.f;
      ssum0 += e00 + e01;
      ssum1 += e10 + e11;
      float2 v0 = make_float2(e00, e01), v1 = make_float2(e10, e11);
      __stcg(reinterpret_cast<float2*>(&strip[r0 * SPn + t * KTn + cb]), v0);
      __stcg(reinterpret_cast<float2*>(&strip[r1 * SPn + t * KTn + cb]), v1);
    }
  }

  // ---- row sums: 4-lane shfl reduce, one atomic per row ----
  ssum0 += __shfl_xor_sync(0xffffffffu, ssum0, 1);
  ssum0 += __shfl_xor_sync(0xffffffffu, ssum0, 2);
  ssum1 += __shfl_xor_sync(0xffffffffu, ssum1, 1);
  ssum1 += __shfl_xor_sync(0xffffffffu, ssum1, 2);
  if ((lane & 3) == 0) {
    atomicAdd(&sums[r0], ssum0);
    atomicAdd(&sums[r1], ssum1);
  }
  __syncthreads();

  // ======================= PV phase =======================
  const float c1a = 1.02f / sums[r0], c1b = 1.02f / sums[r1];
  float oacc[4][4] = {};
  for (int t = 0; t < nt; ++t) {
    const int jb = lo + t * KTn;
    __syncthreads();
    for (int m = tid; m < KTn * 32; m += 256) {
      int r = m >> 5, d4 = m & 31, j = jb + r;
      float4 vv = make_float4(0.f, 0.f, 0.f, 0.f);
      if (j < kend) vv = *reinterpret_cast<const float4*>(vb + (size_t)j * (HKVn * Dn) + 4 * d4);
      uint2 hi, lo2;
      split4(vv, hi, lo2);
      uint32_t off = (uint32_t)(r * PQn + 4 * d4) * 2;
      *reinterpret_cast<uint2*>(sm + O_KH + off) = hi;   // VH
      *reinterpret_cast<uint2*>(sm + O_KL + off) = lo2;  // VL
    }
    __syncthreads();

#pragma unroll
    for (int ks = 0; ks < 8; ++ks) {
      const int colb = t * KTn + 16 * ks + c2;
      float2 p00 = __ldcg(reinterpret_cast<const float2*>(&strip[r0 * SPn + colb]));
      float2 p01 = __ldcg(reinterpret_cast<const float2*>(&strip[r0 * SPn + colb + 8]));
      float2 p10 = __ldcg(reinterpret_cast<const float2*>(&strip[r1 * SPn + colb]));
      float2 p11 = __ldcg(reinterpret_cast<const float2*>(&strip[r1 * SPn + colb + 8]));
      float a00 = fminf(fmaxf(fmaf(p00.x, c1a, -0.01f), 0.f), 1.f);
      float a01 = fminf(fmaxf(fmaf(p00.y, c1a, -0.01f), 0.f), 1.f);
      float a02 = fminf(fmaxf(fmaf(p01.x, c1a, -0.01f), 0.f), 1.f);
      float a03 = fminf(fmaxf(fmaf(p01.y, c1a, -0.01f), 0.f), 1.f);
      float a10 = fminf(fmaxf(fmaf(p10.x, c1b, -0.01f), 0.f), 1.f);
      float a11 = fminf(fmaxf(fmaf(p10.y, c1b, -0.01f), 0.f), 1.f);
      float a12 = fminf(fmaxf(fmaf(p11.x, c1b, -0.01f), 0.f), 1.f);
      float a13 = fminf(fmaxf(fmaf(p11.y, c1b, -0.01f), 0.f), 1.f);
      uint32_t ah[4], al[4];
      split2(a00, a01, ah[0], al[0]);
      split2(a10, a11, ah[1], al[1]);
      split2(a02, a03, ah[2], al[2]);
      split2(a12, a13, ah[3], al[3]);
#pragma unroll
      for (int p = 0; p < 2; ++p) {
        uint32_t bh[4], bl[4];
        uint32_t boff = (uint32_t)((16 * ks + vRow) * PQn + 32 * nb + 16 * p + vColB) * 2;
        ldsm4t(sb + O_KH + boff, bh);
        ldsm4t(sb + O_KL + boff, bl);
        mma16816(oacc[2 * p], ah, bh[0], bh[1]);
        mma16816(oacc[2 * p], ah, bl[0], bl[1]);
        mma16816(oacc[2 * p], al, bh[0], bh[1]);
        mma16816(oacc[2 * p + 1], ah, bh[2], bh[3]);
        mma16816(oacc[2 * p + 1], ah, bl[2], bl[3]);
        mma16816(oacc[2 * p + 1], al, bh[2], bh[3]);
      }
    }
  }

  // ---- stage output through smem (reuse K/V buffer), coalesced store ----
  __syncthreads();
  float* ostage = reinterpret_cast<float*>(sm + O_KH);   // 32 x 132 f32
#pragma unroll
  for (int j4 = 0; j4 < 4; ++j4) {
    const int cb = 32 * nb + 8 * j4 + c2;
    *reinterpret_cast<float2*>(&ostage[r0 * 132 + cb]) = make_float2(oacc[j4][0], oacc[j4][1]);
    *reinterpret_cast<float2*>(&ostage[r1 * 132 + cb]) = make_float2(oacc[j4][2], oacc[j4][3]);
  }
  __syncthreads();
  for (int m = tid; m < QTn * 32; m += 256) {
    int r = m >> 5, d4 = m & 31;
    float* op = out + (((size_t)(b * SQn + qs8 + (r & 7)) * HQn) + kvh * 4 + (r >> 3)) * Dn;
    *reinterpret_cast<float4*>(op + 4 * d4) =
        *reinterpret_cast<const float4*>(&ostage[r * 132 + 4 * d4]);
  }
}

extern "C" void kernel_launch(void* const* d_in, const int* in_sizes, int n_in,
                              void* d_out, int out_size) {
  (void)in_sizes; (void)n_in; (void)out_size;
  const float* q = (const float*)d_in[0];
  const float* k = (const float*)d_in[1];
  const float* v = (const float*)d_in[2];
  float* out = (float*)d_out;
  cudaFuncSetAttribute(swa_mma, cudaFuncAttributeMaxDynamicSharedMemorySize, SMEM_SZ);
  dim3 grid(NQBn, HKVn, 2);
  swa_mma<<<grid, 256, SMEM_SZ>>>(q, k, v, out);
}